// round 7
// baseline (speedup 1.0000x reference)
#include <cuda_runtime.h>

// out[b,q,d] = sum_k values[b,k,d]  (softmax over singleton axis == 1;
// queries/keys/w_score are dead code). B=4, Q=512, K=512, F=128.
//
// Feature-split: block = (batch, 32-float feature slice, 64-row Q slice).
// 128 blocks (one wave), 1024 threads (32 warps/SM) to maximize overlap of
// the L1tex wavefront drain with the DRAM-latency chain. 4 LDG.128/thread,
// shfl fold, single barrier, 512 storing threads with 1 STG.128 each.

#define B_   4
#define Q_   512
#define K_   512
#define F4   32      // float4 per full feature row
#define FSL4 8       // float4 per feature slice (32 floats = 128 B)
#define QROWS 64     // Q rows written per block

__global__ void __launch_bounds__(1024, 1)
feat_split_sum_broadcast(const float4* __restrict__ values,
                         float4* __restrict__ out) {
    __shared__ float4 part[32][FSL4];          // per-warp column partials (4 KB)

    const int b   = blockIdx.x >> 5;           // batch         (0..3)
    const int rem = blockIdx.x & 31;
    const int fsl = rem >> 3;                  // feature slice (0..3)
    const int qsl = rem & 7;                   // Q slice       (0..7)

    const int tid  = threadIdx.x;
    const int w    = tid >> 5;                 // warp 0..31: K rows [w*16, w*16+16)
    const int lane = tid & 31;
    const int c    = lane & 7;                 // float4 column within slice
    const int rsub = lane >> 3;                // row offset 0..3 in a 4-row group

    // ---- Phase 1: each lane streams 4 rows (stride 4) of its column.
    const float4* p = values
        + ((size_t)(b * K_ + w * 16 + rsub)) * F4 + fsl * FSL4 + c;

    float4 v0 = __ldcg(p + 0 * 4 * F4);
    float4 v1 = __ldcg(p + 1 * 4 * F4);
    float4 v2 = __ldcg(p + 2 * 4 * F4);
    float4 v3 = __ldcg(p + 3 * 4 * F4);

    float4 acc;   // depth-2 pairwise tree
    acc.x = (v0.x + v1.x) + (v2.x + v3.x);
    acc.y = (v0.y + v1.y) + (v2.y + v3.y);
    acc.z = (v0.z + v1.z) + (v2.z + v3.z);
    acc.w = (v0.w + v1.w) + (v2.w + v3.w);

    // ---- Phase 2: fold the 4 row-groups sharing a column (xor 8, 16).
#pragma unroll
    for (int m = 8; m <= 16; m <<= 1) {
        acc.x += __shfl_xor_sync(0xffffffffu, acc.x, m);
        acc.y += __shfl_xor_sync(0xffffffffu, acc.y, m);
        acc.z += __shfl_xor_sync(0xffffffffu, acc.z, m);
        acc.w += __shfl_xor_sync(0xffffffffu, acc.w, m);
    }
    if (lane < FSL4) part[w][lane] = acc;
    __syncthreads();

    // ---- Phase 3+4: first 512 threads fold the 32 warp-partials for their
    // column (broadcast LDS, conflict-free) and write one output float4.
    if (tid < 512) {
        float4 s0 = part[0][c], s1 = part[1][c],
               s2 = part[2][c], s3 = part[3][c];
#pragma unroll
        for (int i = 4; i < 32; i += 4) {
            float4 w0 = part[i + 0][c];
            float4 w1 = part[i + 1][c];
            float4 w2 = part[i + 2][c];
            float4 w3 = part[i + 3][c];
            s0.x += w0.x; s0.y += w0.y; s0.z += w0.z; s0.w += w0.w;
            s1.x += w1.x; s1.y += w1.y; s1.z += w1.z; s1.w += w1.w;
            s2.x += w2.x; s2.y += w2.y; s2.z += w2.z; s2.w += w2.w;
            s3.x += w3.x; s3.y += w3.y; s3.z += w3.z; s3.w += w3.w;
        }
        float4 t;
        t.x = (s0.x + s1.x) + (s2.x + s3.x);
        t.y = (s0.y + s1.y) + (s2.y + s3.y);
        t.z = (s0.z + s1.z) + (s2.z + s3.z);
        t.w = (s0.w + s1.w) + (s2.w + s3.w);

        // row = tid/8 within this block's 64-row Q slice, column c.
        const int row = qsl * QROWS + (tid >> 3);
        out[((size_t)(b * Q_ + row)) * F4 + fsl * FSL4 + c] = t;
    }
}

extern "C" void kernel_launch(void* const* d_in, const int* in_sizes, int n_in,
                              void* d_out, int out_size) {
    // inputs (metadata order): queries, keys, values, w_score
    const float4* values = (const float4*)d_in[2];
    float4* out = (float4*)d_out;
    feat_split_sum_broadcast<<<128, 1024>>>(values, out);
}